// round 1
// baseline (speedup 1.0000x reference)
#include <cuda_runtime.h>

// Shapes (fixed by the problem)
#define BD 8
#define LD 4096
#define HD 16
#define ED 64
#define NSPLIT 8
#define ROWS_P1 (LD / NSPLIT)          // 512 rows per pass-1 block
#define PART_STRIDE (ED * ED + ED)     // 4096 KV + 64 k_sum per partial
#define RPB 128                        // rows per pass-2 block

#define NEG_CLAMP -20.0f
#define EPS 1e-6f

// Scratch: per (b,h,split) partial KV (64x64) + partial k_sum (64). ~17 MB.
__device__ __align__(16) float g_part[BD * HD * NSPLIT * PART_STRIDE];

__device__ __forceinline__ float warp_max(float v) {
#pragma unroll
    for (int o = 16; o > 0; o >>= 1)
        v = fmaxf(v, __shfl_xor_sync(0xffffffffu, v, o));
    return v;
}
__device__ __forceinline__ float warp_sum(float v) {
#pragma unroll
    for (int o = 16; o > 0; o >>= 1)
        v += __shfl_xor_sync(0xffffffffu, v, o);
    return v;
}

// ---------------------------------------------------------------------------
// Pass 1: for each (b,h,split): KV_part[d][e] = sum_l softK[l][d] * V[l][e]
//         and ksum_part[e] = sum_l softK[l][e]
// Block: 256 threads. Warp w softmaxes one K row + loads one V row per chunk
// of 8 rows into smem; then every thread accumulates a 4x4 tile of KV.
// ---------------------------------------------------------------------------
__global__ __launch_bounds__(256) void la_pass1(
    const float* __restrict__ keys,
    const float* __restrict__ values,
    const float* __restrict__ delta1)
{
    __shared__ __align__(16) float sk[8][68];
    __shared__ __align__(16) float sv[8][68];
    __shared__ float sks[8][64];

    const int tid  = threadIdx.x;
    const int lane = tid & 31;
    const int w    = tid >> 5;
    const int blk  = blockIdx.x;
    const int split = blk & (NSPLIT - 1);
    const int bh    = blk >> 3;           // NSPLIT == 8
    const int b     = bh >> 4;
    const int h     = bh & 15;

    const float inv_temp = 1.0f / log1pf(__expf(delta1[0]));

    const int te = tid & 15;     // e-tile index (4 cols each)
    const int td = tid >> 4;     // d-tile index (4 rows each)

    float acc[4][4];
#pragma unroll
    for (int i = 0; i < 4; ++i)
#pragma unroll
        for (int j = 0; j < 4; ++j) acc[i][j] = 0.0f;

    float ks0 = 0.0f, ks1 = 0.0f;   // k_sum partials for e = 2*lane, 2*lane+1

    const int row_stride = HD * ED;                   // 1024 floats
    const int base = (b * LD) * row_stride + h * ED;  // fits in int (<=33.5M)
    const int l0 = split * ROWS_P1;

    for (int c = 0; c < ROWS_P1 / 8; ++c) {
        const int l = l0 + c * 8 + w;
        const float* kr = keys   + base + l * row_stride;
        const float* vr = values + base + l * row_stride;

        // --- stage: softmax K row, raw V row -> smem ---
        float2 kx = *(const float2*)(kr + 2 * lane);
        float x0 = (kx.x < 0.0f) ? NEG_CLAMP : kx.x;
        float x1 = (kx.y < 0.0f) ? NEG_CLAMP : kx.y;
        float m = warp_max(fmaxf(x0, x1));
        float e0 = __expf((x0 - m) * inv_temp);
        float e1 = __expf((x1 - m) * inv_temp);
        float s  = warp_sum(e0 + e1);
        float inv = 1.0f / s;
        float n0 = e0 * inv, n1 = e1 * inv;
        ks0 += n0; ks1 += n1;
        *(float2*)&sk[w][2 * lane] = make_float2(n0, n1);

        float2 vx = *(const float2*)(vr + 2 * lane);
        *(float2*)&sv[w][2 * lane] = vx;
        __syncthreads();

        // --- accumulate 8 rank-1 updates into 4x4 register tile ---
#pragma unroll
        for (int r = 0; r < 8; ++r) {
            float4 kk = *(const float4*)&sk[r][4 * td];
            float4 vv = *(const float4*)&sv[r][4 * te];
            acc[0][0] += kk.x * vv.x; acc[0][1] += kk.x * vv.y;
            acc[0][2] += kk.x * vv.z; acc[0][3] += kk.x * vv.w;
            acc[1][0] += kk.y * vv.x; acc[1][1] += kk.y * vv.y;
            acc[1][2] += kk.y * vv.z; acc[1][3] += kk.y * vv.w;
            acc[2][0] += kk.z * vv.x; acc[2][1] += kk.z * vv.y;
            acc[2][2] += kk.z * vv.z; acc[2][3] += kk.z * vv.w;
            acc[3][0] += kk.w * vv.x; acc[3][1] += kk.w * vv.y;
            acc[3][2] += kk.w * vv.z; acc[3][3] += kk.w * vv.w;
        }
        __syncthreads();
    }

    // --- write KV partial ---
    float* dst = g_part + (bh * NSPLIT + split) * PART_STRIDE;
#pragma unroll
    for (int i = 0; i < 4; ++i) {
        float4 o = make_float4(acc[i][0], acc[i][1], acc[i][2], acc[i][3]);
        *(float4*)&dst[(4 * td + i) * ED + 4 * te] = o;
    }

    // --- reduce k_sum across warps, write partial ---
    sks[w][2 * lane]     = ks0;
    sks[w][2 * lane + 1] = ks1;
    __syncthreads();
    if (tid < ED) {
        float s = 0.0f;
#pragma unroll
        for (int ww = 0; ww < 8; ++ww) s += sks[ww][tid];
        dst[ED * ED + tid] = s;
    }
}

// ---------------------------------------------------------------------------
// Pass 2: out[l][e] = z_l * sum_d softQ[l][d] * KV[d][e]
//         z_l = 1 / (softQ[l] . k_sum + EPS), folded into staged q.
// Block: 256 threads, 128 rows of one (b,h). KV + k_sum summed from 8
// partials into smem, then two 64-row tiles.
// ---------------------------------------------------------------------------
__global__ __launch_bounds__(256) void la_pass2(
    const float* __restrict__ queries,
    const float* __restrict__ delta1,
    float* __restrict__ out)
{
    __shared__ __align__(16) float skv[ED * 68];   // [d][e], stride 68
    __shared__ __align__(16) float sq[64 * 68];    // [row][d], stride 68
    __shared__ float sksum[ED];

    const int tid  = threadIdx.x;
    const int lane = tid & 31;
    const int w    = tid >> 5;
    const int blk  = blockIdx.x;
    const int rb   = blk & 31;             // 4096/128 = 32 row-blocks
    const int bh   = blk >> 5;
    const int b    = bh >> 4;
    const int h    = bh & 15;

    const float inv_temp = 1.0f / log1pf(__expf(delta1[0]));

    // --- load & sum the 8 KV partials ---
    const float* part = g_part + bh * NSPLIT * PART_STRIDE;
    for (int j = tid; j < 1024; j += 256) {        // float4 index over 4096
        float4 a = make_float4(0.f, 0.f, 0.f, 0.f);
#pragma unroll
        for (int p = 0; p < NSPLIT; ++p) {
            float4 t = *(const float4*)&part[p * PART_STRIDE + j * 4];
            a.x += t.x; a.y += t.y; a.z += t.z; a.w += t.w;
        }
        const int d = j >> 4, col = (j & 15) * 4;
        *(float4*)&skv[d * 68 + col] = a;
    }
    if (tid < ED) {
        float s = 0.0f;
#pragma unroll
        for (int p = 0; p < NSPLIT; ++p) s += part[p * PART_STRIDE + ED * ED + tid];
        sksum[tid] = s;
    }
    __syncthreads();

    const int row_stride = HD * ED;
    const int base = (b * LD) * row_stride + h * ED;
    const int l0 = rb * RPB;

    const int te = tid & 15;
    const int tr = tid >> 4;
    const int tr4 = 4 * tr;

    for (int it = 0; it < RPB / 64; ++it) {
        // --- stage: softmax Q rows, fold z ---
#pragma unroll 1
        for (int j = 0; j < 8; ++j) {
            const int rr = w + 8 * j;
            const int l = l0 + it * 64 + rr;
            const float* qr = queries + base + l * row_stride;
            float2 qx = *(const float2*)(qr + 2 * lane);
            float x0 = (qx.x < 0.0f) ? NEG_CLAMP : qx.x;
            float x1 = (qx.y < 0.0f) ? NEG_CLAMP : qx.y;
            float m = warp_max(fmaxf(x0, x1));
            float e0 = __expf((x0 - m) * inv_temp);
            float e1 = __expf((x1 - m) * inv_temp);
            float s  = warp_sum(e0 + e1);
            float inv = 1.0f / s;
            float n0 = e0 * inv, n1 = e1 * inv;
            float dp = warp_sum(n0 * sksum[2 * lane] + n1 * sksum[2 * lane + 1]);
            float z = 1.0f / (dp + EPS);
            *(float2*)&sq[rr * 68 + 2 * lane] = make_float2(n0 * z, n1 * z);
        }
        __syncthreads();

        // --- 4x4 thread-tile vec-mat: rows tr4..tr4+3, cols 4*te.. ---
        float acc[4][4];
#pragma unroll
        for (int i = 0; i < 4; ++i)
#pragma unroll
            for (int j = 0; j < 4; ++j) acc[i][j] = 0.0f;

#pragma unroll 16
        for (int d = 0; d < ED; ++d) {
            float4 kvv = *(const float4*)&skv[d * 68 + 4 * te];
            float q0 = sq[(tr4 + 0) * 68 + d];
            float q1 = sq[(tr4 + 1) * 68 + d];
            float q2 = sq[(tr4 + 2) * 68 + d];
            float q3 = sq[(tr4 + 3) * 68 + d];
            acc[0][0] += q0 * kvv.x; acc[0][1] += q0 * kvv.y;
            acc[0][2] += q0 * kvv.z; acc[0][3] += q0 * kvv.w;
            acc[1][0] += q1 * kvv.x; acc[1][1] += q1 * kvv.y;
            acc[1][2] += q1 * kvv.z; acc[1][3] += q1 * kvv.w;
            acc[2][0] += q2 * kvv.x; acc[2][1] += q2 * kvv.y;
            acc[2][2] += q2 * kvv.z; acc[2][3] += q2 * kvv.w;
            acc[3][0] += q3 * kvv.x; acc[3][1] += q3 * kvv.y;
            acc[3][2] += q3 * kvv.z; acc[3][3] += q3 * kvv.w;
        }

        // --- coalesced float4 stores ---
#pragma unroll
        for (int i = 0; i < 4; ++i) {
            const int l = l0 + it * 64 + tr4 + i;
            float4 o = make_float4(acc[i][0], acc[i][1], acc[i][2], acc[i][3]);
            *(float4*)&out[base + l * row_stride + 4 * te] = o;
        }
        __syncthreads();   // sq reused next iteration
    }
}

extern "C" void kernel_launch(void* const* d_in, const int* in_sizes, int n_in,
                              void* d_out, int out_size) {
    const float* queries = (const float*)d_in[0];
    const float* keys    = (const float*)d_in[1];
    const float* values  = (const float*)d_in[2];
    const float* delta1  = (const float*)d_in[3];
    float* out = (float*)d_out;

    la_pass1<<<BD * HD * NSPLIT, 256>>>(keys, values, delta1);
    la_pass2<<<BD * HD * (LD / RPB), 256>>>(queries, delta1, out);
}

// round 7
// speedup vs baseline: 1.0523x; 1.0523x over previous
#include <cuda_runtime.h>
#include <cuda_bf16.h>
#include <cstdint>

// Shapes (fixed by the problem)
#define BD 8
#define LD 4096
#define HD 16
#define ED 64
#define NSPLIT 4
#define ROWS_P1 (LD / NSPLIT)          // 1024 rows per pass-1 CTA
#define PART_STRIDE (ED * ED + ED)     // 4096 KV + 64 k_sum per partial

#define NEG_CLAMP -20.0f
#define EPS 1e-6f

// Scratch (device globals; allocation APIs are banned)
__device__ __align__(16)   float          g_part[BD * HD * NSPLIT * PART_STRIDE];
__device__ __align__(1024) unsigned short g_kvb_hi[BD * HD * ED * ED];  // pre-swizzled bf16 [d][e]
__device__ __align__(1024) unsigned short g_kvb_lo[BD * HD * ED * ED];
__device__                 float          g_ksum[BD * HD * ED];

// SW128-style XOR swizzle for 128B rows: o = row*128 + colbytes
#define SWZ(o) ((o) ^ (((o) >> 3) & 0x70))

__device__ __forceinline__ uint32_t smem_u32(const void* p) {
    uint32_t a;
    asm("{ .reg .u64 t; cvta.to.shared.u64 t, %1; cvt.u32.u64 %0, t; }" : "=r"(a) : "l"(p));
    return a;
}

// ---- base-target tensor ops (no 'a'-suffix features!) ----
__device__ __forceinline__ void ldsm_x4(uint32_t* r, uint32_t addr) {
    asm volatile("ldmatrix.sync.aligned.m8n8.x4.shared.b16 {%0,%1,%2,%3}, [%4];"
        : "=r"(r[0]), "=r"(r[1]), "=r"(r[2]), "=r"(r[3]) : "r"(addr));
}
__device__ __forceinline__ void ldsm_x4_t(uint32_t* r, uint32_t addr) {
    asm volatile("ldmatrix.sync.aligned.m8n8.x4.trans.shared.b16 {%0,%1,%2,%3}, [%4];"
        : "=r"(r[0]), "=r"(r[1]), "=r"(r[2]), "=r"(r[3]) : "r"(addr));
}
__device__ __forceinline__ void mma16816(float* c, const uint32_t* a, const uint32_t* b) {
    asm volatile("mma.sync.aligned.m16n8k16.row.col.f32.bf16.bf16.f32 "
        "{%0,%1,%2,%3}, {%4,%5,%6,%7}, {%8,%9}, {%0,%1,%2,%3};"
        : "+f"(c[0]), "+f"(c[1]), "+f"(c[2]), "+f"(c[3])
        : "r"(a[0]), "r"(a[1]), "r"(a[2]), "r"(a[3]), "r"(b[0]), "r"(b[1]));
}

__device__ __forceinline__ uint32_t pack_split_hi(float x0, float x1, uint32_t& lo_pack) {
    __nv_bfloat16 h0 = __float2bfloat16(x0);
    __nv_bfloat16 h1 = __float2bfloat16(x1);
    __nv_bfloat16 l0 = __float2bfloat16(x0 - __bfloat162float(h0));
    __nv_bfloat16 l1 = __float2bfloat16(x1 - __bfloat162float(h1));
    lo_pack = ((uint32_t)__bfloat16_as_ushort(l1) << 16) | __bfloat16_as_ushort(l0);
    return ((uint32_t)__bfloat16_as_ushort(h1) << 16) | __bfloat16_as_ushort(h0);
}

__device__ __forceinline__ float warp_sum(float v) {
#pragma unroll
    for (int o = 16; o > 0; o >>= 1)
        v += __shfl_xor_sync(0xffffffffu, v, o);
    return v;
}

// ---------------------------------------------------------------------------
// Pass 1: per (b,h,split) partial KV[64x64] = softK^T V over 1024 l-rows.
// 128 threads / 4 warps. Chunked: stage 64 rows (K softmaxed + V, bf16 hi/lo,
// swizzled), then mma. Warp w owns d-rows [w*16, w*16+16), all 64 e-cols.
// ---------------------------------------------------------------------------
#define P1_KH 0
#define P1_KL 8192
#define P1_VH 16384
#define P1_VL 24576

__global__ __launch_bounds__(128) void la_pass1(
    const float* __restrict__ keys,
    const float* __restrict__ values,
    const float* __restrict__ delta1)
{
    __shared__ __align__(1024) char sm[32768];
    __shared__ float sks[4][64];
    const uint32_t sb = smem_u32(sm);

    const int tid  = threadIdx.x;
    const int lane = tid & 31;
    const int w    = tid >> 5;
    const int blk  = blockIdx.x;
    const int split = blk & (NSPLIT - 1);
    const int bh    = blk >> 2;
    const int b     = bh >> 4;
    const int h     = bh & 15;

    const int g = lane >> 2, t = lane & 3;
    const int r8  = lane & 7;
    const int qb0 = (lane >> 3) & 1;
    const int qb1 = (lane >> 4) & 1;

    const float inv_temp = 1.0f / log1pf(__expf(delta1[0]));

    float acc[8][4];
#pragma unroll
    for (int i = 0; i < 8; ++i)
#pragma unroll
        for (int j = 0; j < 4; ++j) acc[i][j] = 0.0f;

    float ks0 = 0.0f, ks1 = 0.0f;

    const int row_stride = HD * ED;
    const int base = (b * LD) * row_stride + h * ED;
    const int l0 = split * ROWS_P1;

    for (int ch = 0; ch < ROWS_P1 / 64; ++ch) {
        // ---- stage 16 rows per warp: softmax-K (hi/lo) + V (hi/lo) ----
#pragma unroll 2
        for (int j = 0; j < 16; ++j) {
            const int rl = w * 16 + j;
            const int l  = l0 + ch * 64 + rl;
            const float* kr = keys   + base + l * row_stride;
            const float* vr = values + base + l * row_stride;

            float2 kx = *(const float2*)(kr + 2 * lane);
            float x0 = (kx.x < 0.0f) ? NEG_CLAMP : kx.x;
            float x1 = (kx.y < 0.0f) ? NEG_CLAMP : kx.y;
            float e0 = __expf(x0 * inv_temp);
            float e1 = __expf(x1 * inv_temp);
            float s  = warp_sum(e0 + e1);
            float inv = 1.0f / s;
            float n0 = e0 * inv, n1 = e1 * inv;
            ks0 += n0; ks1 += n1;

            const uint32_t off = SWZ((uint32_t)(rl * 128 + lane * 4));
            uint32_t lp, hp = pack_split_hi(n0, n1, lp);
            *(uint32_t*)(sm + P1_KH + off) = hp;
            *(uint32_t*)(sm + P1_KL + off) = lp;

            float2 vx = *(const float2*)(vr + 2 * lane);
            hp = pack_split_hi(vx.x, vx.y, lp);
            *(uint32_t*)(sm + P1_VH + off) = hp;
            *(uint32_t*)(sm + P1_VL + off) = lp;
        }
        __syncthreads();

        // ---- GEMM over this chunk: 4 k-steps of 16 ----
#pragma unroll
        for (int ks = 0; ks < 4; ++ks) {
            const int kloc = ks * 16;
            // A = softK^T : trans-ldmatrix from [l][d] tile
            const int arow = kloc + r8 + 8 * qb1;
            const uint32_t amask = (uint32_t)((arow & 7) << 4);
            const uint32_t aoff = (uint32_t)(arow * 128) + (((uint32_t)(32 * w + 16 * qb0)) ^ amask);
            uint32_t aH[4], aL[4];
            ldsm_x4_t(aH, sb + P1_KH + aoff);
            ldsm_x4_t(aL, sb + P1_KL + aoff);

            const int brow = kloc + r8 + 8 * qb0;
            const uint32_t bmask = (uint32_t)((brow & 7) << 4);
#pragma unroll
            for (int nb = 0; nb < 4; ++nb) {
                const uint32_t boff = (uint32_t)(brow * 128) + (((uint32_t)(nb * 32 + 16 * qb1)) ^ bmask);
                uint32_t bH[4], bL[4];
                ldsm_x4_t(bH, sb + P1_VH + boff);
                ldsm_x4_t(bL, sb + P1_VL + boff);
#pragma unroll
                for (int sub = 0; sub < 2; ++sub) {
                    float* c = acc[nb * 2 + sub];
                    mma16816(c, aH, bH + 2 * sub);
                    mma16816(c, aH, bL + 2 * sub);
                    mma16816(c, aL, bH + 2 * sub);
                }
            }
        }
        __syncthreads();
    }

    // ---- write KV partial (fp32) ----
    float* dst = g_part + (bh * NSPLIT + split) * PART_STRIDE;
    const int d0 = w * 16 + g;
#pragma unroll
    for (int nt = 0; nt < 8; ++nt) {
        const int e = nt * 8 + 2 * t;
        *(float2*)&dst[d0 * ED + e]       = make_float2(acc[nt][0], acc[nt][1]);
        *(float2*)&dst[(d0 + 8) * ED + e] = make_float2(acc[nt][2], acc[nt][3]);
    }

    // ---- ksum partial ----
    sks[w][2 * lane]     = ks0;
    sks[w][2 * lane + 1] = ks1;
    __syncthreads();
    if (tid < ED) {
        float s = sks[0][tid] + sks[1][tid] + sks[2][tid] + sks[3][tid];
        dst[ED * ED + tid] = s;
    }
}

// ---------------------------------------------------------------------------
// Reduce: sum NSPLIT partials once per (b,h) -> pre-swizzled bf16 hi/lo KV
// tiles (row-major [d][e], 128B rows, SWZ) + fp32 ksum.
// ---------------------------------------------------------------------------
__global__ __launch_bounds__(256) void la_reduce()
{
    const int bh = blockIdx.x;
    const int tid = threadIdx.x;
    const float* part = g_part + bh * NSPLIT * PART_STRIDE;
    char* dsth = (char*)(g_kvb_hi + bh * ED * ED);
    char* dstl = (char*)(g_kvb_lo + bh * ED * ED);

    for (int idx = tid; idx < ED * ED; idx += 256) {
        float s = 0.0f;
#pragma unroll
        for (int p = 0; p < NSPLIT; ++p) s += part[p * PART_STRIDE + idx];
        const int d = idx >> 6, e = idx & 63;
        __nv_bfloat16 hi = __float2bfloat16(s);
        __nv_bfloat16 lo = __float2bfloat16(s - __bfloat162float(hi));
        const uint32_t off = SWZ((uint32_t)(d * 128 + e * 2));
        *(unsigned short*)(dsth + off) = __bfloat16_as_ushort(hi);
        *(unsigned short*)(dstl + off) = __bfloat16_as_ushort(lo);
    }
    if (tid < ED) {
        float s = 0.0f;
#pragma unroll
        for (int p = 0; p < NSPLIT; ++p) s += part[p * PART_STRIDE + ED * ED + tid];
        g_ksum[bh * ED + tid] = s;
    }
}

// ---------------------------------------------------------------------------
// Pass 2: out[128 x 64] = (z-folded softQ)[128 x 64] x KV[64 x 64], per CTA.
// 128 threads / 4 warps. Warp w owns rows [w*32, w*32+32) = 2 m-tiles.
// ---------------------------------------------------------------------------
#define P2_AH 0
#define P2_AL 16384
#define P2_BH 32768
#define P2_BL 40960

__global__ __launch_bounds__(128) void la_pass2(
    const float* __restrict__ queries,
    const float* __restrict__ delta1,
    float* __restrict__ out)
{
    __shared__ __align__(1024) char sm[49152];
    const uint32_t sb = smem_u32(sm);

    const int tid  = threadIdx.x;
    const int lane = tid & 31;
    const int w    = tid >> 5;
    const int blk  = blockIdx.x;
    const int rb   = blk & 31;
    const int bh   = blk >> 5;
    const int b    = bh >> 4;
    const int h    = bh & 15;

    const int g = lane >> 2, t = lane & 3;
    const int r8  = lane & 7;
    const int qb0 = (lane >> 3) & 1;
    const int qb1 = (lane >> 4) & 1;

    // ---- copy pre-swizzled B tiles from global (swizzle-preserving) ----
    {
        const uint4* srcH = (const uint4*)(g_kvb_hi + bh * ED * ED);
        const uint4* srcL = (const uint4*)(g_kvb_lo + bh * ED * ED);
        uint4* dH = (uint4*)(sm + P2_BH);
        uint4* dL = (uint4*)(sm + P2_BL);
#pragma unroll
        for (int i = tid; i < 512; i += 128) { dH[i] = srcH[i]; dL[i] = srcL[i]; }
    }

    const float ksa = g_ksum[bh * ED + 2 * lane];
    const float ksb = g_ksum[bh * ED + 2 * lane + 1];
    const float inv_temp = 1.0f / log1pf(__expf(delta1[0]));

    const int row_stride = HD * ED;
    const int base = (b * LD) * row_stride + h * ED;
    const int l0 = rb * 128;

    // ---- stage A: softmax Q rows, fold z, split hi/lo ----
#pragma unroll 4
    for (int j = 0; j < 32; ++j) {
        const int r = w * 32 + j;
        const float* qr = queries + base + (l0 + r) * row_stride;
        float2 qx = *(const float2*)(qr + 2 * lane);
        float x0 = (qx.x < 0.0f) ? NEG_CLAMP : qx.x;
        float x1 = (qx.y < 0.0f) ? NEG_CLAMP : qx.y;
        float e0 = __expf(x0 * inv_temp);
        float e1 = __expf(x1 * inv_temp);
        float s  = e0 + e1;
        float dp = e0 * ksa + e1 * ksb;
#pragma unroll
        for (int o = 16; o > 0; o >>= 1) {
            s  += __shfl_xor_sync(0xffffffffu, s,  o);
            dp += __shfl_xor_sync(0xffffffffu, dp, o);
        }
        const float scale = 1.0f / (dp + EPS * s);   // (e/s)/(dp/s+EPS) = e/(dp+EPS*s)
        uint32_t lp, hp = pack_split_hi(e0 * scale, e1 * scale, lp);
        const uint32_t off = SWZ((uint32_t)(r * 128 + lane * 4));
        *(uint32_t*)(sm + P2_AH + off) = hp;
        *(uint32_t*)(sm + P2_AL + off) = lp;
    }
    __syncthreads();

    // ---- GEMM: M=32 per warp (2 m-tiles), N=64, K=64 ----
    float acc[2][8][4];
#pragma unroll
    for (int mt = 0; mt < 2; ++mt)
#pragma unroll
        for (int nt = 0; nt < 8; ++nt)
#pragma unroll
            for (int j = 0; j < 4; ++j) acc[mt][nt][j] = 0.0f;

#pragma unroll
    for (int ks = 0; ks < 4; ++ks) {
        uint32_t aH[2][4], aL[2][4];
#pragma unroll
        for (int mt = 0; mt < 2; ++mt) {
            const int arow = w * 32 + mt * 16 + r8 + 8 * qb0;
            const uint32_t amask = (uint32_t)((arow & 7) << 4);
            const uint32_t aoff = (uint32_t)(arow * 128) + (((uint32_t)(ks * 32 + 16 * qb1)) ^ amask);
            ldsm_x4(aH[mt], sb + P2_AH + aoff);
            ldsm_x4(aL[mt], sb + P2_AL + aoff);
        }
        const int brow = ks * 16 + r8 + 8 * qb0;
        const uint32_t bmask = (uint32_t)((brow & 7) << 4);
#pragma unroll
        for (int nb = 0; nb < 4; ++nb) {
            const uint32_t boff = (uint32_t)(brow * 128) + (((uint32_t)(nb * 32 + 16 * qb1)) ^ bmask);
            uint32_t bH[4], bL[4];
            ldsm_x4_t(bH, sb + P2_BH + boff);
            ldsm_x4_t(bL, sb + P2_BL + boff);
#pragma unroll
            for (int mt = 0; mt < 2; ++mt)
#pragma unroll
                for (int sub = 0; sub < 2; ++sub) {
                    float* c = acc[mt][nb * 2 + sub];
                    mma16816(c, aH[mt], bH + 2 * sub);
                    mma16816(c, aH[mt], bL + 2 * sub);
                    mma16816(c, aL[mt], bH + 2 * sub);
                }
        }
    }

    // ---- epilogue: c-frags straight to gmem (float2, 32B sectors) ----
#pragma unroll
    for (int mt = 0; mt < 2; ++mt) {
        const int r0 = l0 + w * 32 + mt * 16 + g;
        float* o0 = out + base + r0 * row_stride;
        float* o1 = o0 + 8 * row_stride;
#pragma unroll
        for (int nt = 0; nt < 8; ++nt) {
            const int e = nt * 8 + 2 * t;
            *(float2*)(o0 + e) = make_float2(acc[mt][nt][0], acc[mt][nt][1]);
            *(float2*)(o1 + e) = make_float2(acc[mt][nt][2], acc[mt][nt][3]);
        }
    }
}

extern "C" void kernel_launch(void* const* d_in, const int* in_sizes, int n_in,
                              void* d_out, int out_size) {
    const float* queries = (const float*)d_in[0];
    const float* keys    = (const float*)d_in[1];
    const float* values  = (const float*)d_in[2];
    const float* delta1  = (const float*)d_in[3];
    float* out = (float*)d_out;

    la_pass1<<<BD * HD * NSPLIT, 128>>>(keys, values, delta1);
    la_reduce<<<BD * HD, 256>>>();
    la_pass2<<<BD * HD * 32, 128>>>(queries, delta1, out);
}